// round 3
// baseline (speedup 1.0000x reference)
#include <cuda_runtime.h>
#include <cuda_fp16.h>
#include <cstdint>
#include <cstddef>

// ---------------------------------------------------------------------------
// out = sigmoid(relu(x @ W1 + b1) @ W2 + b2)
//   x [4096,2048] f32, W1 [2048,8192] f32, b1 [8192], W2 [8192,2048] f32, b2 [2048]
// tcgen05 is unavailable (harness PTX targets base sm_103, not sm_103a), so:
// fp16 mma.sync (HMMA) GEMMs, fp32 accum, cp.async double-buffer pipeline.
// ---------------------------------------------------------------------------

#define DI __device__ __forceinline__

static constexpr int BATCH = 4096;
static constexpr int IN_F  = 2048;
static constexpr int HID_F = 8192;
static constexpr int OUT_F = 2048;

// fp16 scratch (device globals: allocation-free)
__device__ __align__(16) __half g_x  [(size_t)BATCH * IN_F];   // A of GEMM1 [M,K]
__device__ __align__(16) __half g_w1t[(size_t)HID_F * IN_F];   // B of GEMM1 [N,K]
__device__ __align__(16) __half g_w2t[(size_t)OUT_F * HID_F];  // B of GEMM2 [N,K]
__device__ __align__(16) __half g_h  [(size_t)BATCH * HID_F];  // A of GEMM2 [M,K]

// ---------------------------------------------------------------------------
DI uint32_t smem_u32(const void* p) {
    uint32_t a;
    asm("{ .reg .u64 t; cvta.to.shared.u64 t, %1; cvt.u32.u64 %0, t; }"
        : "=r"(a) : "l"(p));
    return a;
}

DI void cp_async16(uint32_t dst, const void* src) {
    asm volatile("cp.async.cg.shared.global [%0], [%1], 16;"
                 :: "r"(dst), "l"(src) : "memory");
}
DI void cp_commit() { asm volatile("cp.async.commit_group;" ::: "memory"); }
template <int N> DI void cp_wait() {
    asm volatile("cp.async.wait_group %0;" :: "n"(N) : "memory");
}

DI void ldm4(uint32_t* r, uint32_t addr) {
    asm volatile("ldmatrix.sync.aligned.m8n8.x4.shared.b16 {%0,%1,%2,%3}, [%4];"
                 : "=r"(r[0]), "=r"(r[1]), "=r"(r[2]), "=r"(r[3]) : "r"(addr));
}

DI void mma16816(float* d, const uint32_t* a, uint32_t b0, uint32_t b1) {
    asm volatile(
        "mma.sync.aligned.m16n8k16.row.col.f32.f16.f16.f32 "
        "{%0,%1,%2,%3}, {%4,%5,%6,%7}, {%8,%9}, {%0,%1,%2,%3};"
        : "+f"(d[0]), "+f"(d[1]), "+f"(d[2]), "+f"(d[3])
        : "r"(a[0]), "r"(a[1]), "r"(a[2]), "r"(a[3]), "r"(b0), "r"(b1));
}

DI uint32_t sw128(uint32_t o) { return o ^ ((o >> 3) & 0x70); }

// ---------------------------------------------------------------------------
// Convert / transpose kernels (fp32 -> fp16)
// ---------------------------------------------------------------------------
__global__ void convert_x_kernel(const float* __restrict__ x) {
    size_t i = ((size_t)blockIdx.x * 256 + threadIdx.x) * 4;
    float4 v = *reinterpret_cast<const float4*>(x + i);
    __half2* dst = reinterpret_cast<__half2*>(&g_x[i]);
    dst[0] = __floats2half2_rn(v.x, v.y);
    dst[1] = __floats2half2_rn(v.z, v.w);
}

// W [K,N] f32 row-major -> Wt [N,K] fp16 row-major
template <int WHICH>
__global__ void transpose_kernel(const float* __restrict__ W) {
    constexpr int K = WHICH ? HID_F : IN_F;
    constexpr int N = WHICH ? OUT_F : HID_F;
    __half* Wt = WHICH ? g_w2t : g_w1t;
    __shared__ float tile[32][33];
    int n0 = blockIdx.x * 32;
    int k0 = blockIdx.y * 32;
    int tx = threadIdx.x, ty = threadIdx.y;   // (32, 8)
#pragma unroll
    for (int j = 0; j < 32; j += 8)
        tile[ty + j][tx] = W[(size_t)(k0 + ty + j) * N + n0 + tx];
    __syncthreads();
#pragma unroll
    for (int j = 0; j < 32; j += 8)
        Wt[(size_t)(n0 + ty + j) * K + k0 + tx] = __float2half(tile[tx][ty + j]);
}

// ---------------------------------------------------------------------------
// GEMM: per-CTA 128x128, K-chunk 64, fp16 HMMA, fp32 accum.
// 256 threads = 8 warps as 4(M) x 2(N); warp tile 32x64.
// EPI=0: +b1, relu, fp16 -> g_h.  EPI=1: +b2, sigmoid, f32 -> out.
// ---------------------------------------------------------------------------
static constexpr int TILE_BYTES  = 128 * 128;          // 16 KB (128 rows x 64 fp16)
static constexpr int STAGE_BYTES = 2 * TILE_BYTES;     // A + B
static constexpr int SMEM_DYN    = 1024 + 2 * STAGE_BYTES;

DI void load_tile(uint32_t sdst, const char* g, size_t ldb, int tid) {
    // 128 rows x 128 bytes, 16B chunks, SW128 swizzle; 4 chunks per thread
#pragma unroll
    for (int i = 0; i < 4; ++i) {
        int idx = tid + i * 256;          // 0..1023
        int row = idx >> 3;
        int c   = idx & 7;
        uint32_t o = (uint32_t)(row * 128 + c * 16);
        cp_async16(sdst + sw128(o), g + (size_t)row * ldb + c * 16);
    }
}

template <int EPI>
__global__ __launch_bounds__(256, 2)
void gemm_kernel(const float* __restrict__ bias, float* __restrict__ out_f32) {
    constexpr int KDIM  = EPI ? HID_F : IN_F;
    constexpr int NITER = KDIM / 64;
    constexpr size_t LDB = (size_t)KDIM * 2;   // row stride in bytes
    const __half* A = EPI ? g_h   : g_x;
    const __half* B = EPI ? g_w2t : g_w1t;

    extern __shared__ char smem_raw[];
    const uint32_t sbase = (smem_u32(smem_raw) + 1023) & ~1023u;

    const int tid  = threadIdx.x;
    const int lane = tid & 31;
    const int warp = tid >> 5;
    const int wm   = warp & 3;    // 4 warps along M (32 rows each)
    const int wn   = warp >> 2;   // 2 warps along N (64 cols each)
    const int mBase = blockIdx.y * 128;
    const int nBase = blockIdx.x * 128;

    const char* gA = (const char*)(A + (size_t)mBase * KDIM);
    const char* gB = (const char*)(B + (size_t)nBase * KDIM);

    float acc[2][8][4];
#pragma unroll
    for (int i = 0; i < 2; ++i)
#pragma unroll
        for (int j = 0; j < 8; ++j)
#pragma unroll
            for (int k = 0; k < 4; ++k) acc[i][j][k] = 0.0f;

    // prologue: stage 0
    load_tile(sbase,              gA, LDB, tid);
    load_tile(sbase + TILE_BYTES, gB, LDB, tid);
    cp_commit();

    // ldmatrix address components (constant across iters except stage base)
    const uint32_t aRowOff = (uint32_t)((wm * 32 + (lane & 15)) * 128 + ((lane >> 4) << 4));
    const uint32_t bRowOff = (uint32_t)((wn * 64 + (lane & 15)) * 128 + ((lane >> 4) << 4));

#pragma unroll 1
    for (int it = 0; it < NITER; ++it) {
        __syncthreads();   // protect stage being overwritten below from prior readers
        if (it + 1 < NITER) {
            const uint32_t sNext = sbase + ((it + 1) & 1) * STAGE_BYTES;
            const size_t kOff = (size_t)(it + 1) * 128;   // 64 fp16 = 128 bytes
            load_tile(sNext,              gA + kOff, LDB, tid);
            load_tile(sNext + TILE_BYTES, gB + kOff, LDB, tid);
            cp_commit();
            cp_wait<1>();   // stage `it` complete
        } else {
            cp_wait<0>();
        }
        __syncthreads();

        const uint32_t As = sbase + (it & 1) * STAGE_BYTES;
        const uint32_t Bs = As + TILE_BYTES;

#pragma unroll
        for (int ks = 0; ks < 4; ++ks) {
            uint32_t a[2][4], b[4][4];
            const uint32_t koff = ks * 32;
#pragma unroll
            for (int mt = 0; mt < 2; ++mt)
                ldm4(a[mt], As + sw128(aRowOff + mt * 16 * 128 + koff));
#pragma unroll
            for (int nt2 = 0; nt2 < 4; ++nt2)
                ldm4(b[nt2], Bs + sw128(bRowOff + nt2 * 16 * 128 + koff));
#pragma unroll
            for (int mt = 0; mt < 2; ++mt)
#pragma unroll
                for (int nt = 0; nt < 8; ++nt) {
                    const uint32_t* bb = b[nt >> 1];
                    if (nt & 1) mma16816(acc[mt][nt], a[mt], bb[1], bb[3]);
                    else        mma16816(acc[mt][nt], a[mt], bb[0], bb[2]);
                }
        }
    }

    // epilogue
#pragma unroll
    for (int mt = 0; mt < 2; ++mt) {
#pragma unroll
        for (int nt = 0; nt < 8; ++nt) {
            const int col = nBase + wn * 64 + nt * 8 + (lane & 3) * 2;
            const float bv0 = __ldg(&bias[col]);
            const float bv1 = __ldg(&bias[col + 1]);
#pragma unroll
            for (int rr = 0; rr < 2; ++rr) {
                const int row = mBase + wm * 32 + mt * 16 + (lane >> 2) + rr * 8;
                float v0 = acc[mt][nt][rr * 2 + 0] + bv0;
                float v1 = acc[mt][nt][rr * 2 + 1] + bv1;
                if (EPI == 0) {
                    __half2 h = __floats2half2_rn(fmaxf(v0, 0.0f), fmaxf(v1, 0.0f));
                    *reinterpret_cast<__half2*>(&g_h[(size_t)row * HID_F + col]) = h;
                } else {
                    float2 o;
                    o.x = 1.0f / (1.0f + __expf(-v0));
                    o.y = 1.0f / (1.0f + __expf(-v1));
                    *reinterpret_cast<float2*>(&out_f32[(size_t)row * OUT_F + col]) = o;
                }
            }
        }
    }
}

// ---------------------------------------------------------------------------
extern "C" void kernel_launch(void* const* d_in, const int* in_sizes, int n_in,
                              void* d_out, int out_size) {
    (void)in_sizes; (void)n_in; (void)out_size;
    const float* x  = (const float*)d_in[0];
    const float* W1 = (const float*)d_in[1];
    const float* b1 = (const float*)d_in[2];
    const float* W2 = (const float*)d_in[3];
    const float* b2 = (const float*)d_in[4];
    float* out = (float*)d_out;

    cudaFuncSetAttribute(gemm_kernel<0>, cudaFuncAttributeMaxDynamicSharedMemorySize, SMEM_DYN);
    cudaFuncSetAttribute(gemm_kernel<1>, cudaFuncAttributeMaxDynamicSharedMemorySize, SMEM_DYN);

    convert_x_kernel<<<(BATCH * IN_F) / (256 * 4), 256>>>(x);
    transpose_kernel<0><<<dim3(HID_F / 32, IN_F / 32), dim3(32, 8)>>>(W1);
    transpose_kernel<1><<<dim3(OUT_F / 32, HID_F / 32), dim3(32, 8)>>>(W2);

    // GEMM1: H = relu(x @ W1 + b1) -> fp16 g_h
    gemm_kernel<0><<<dim3(HID_F / 128, BATCH / 128), 256, SMEM_DYN>>>(b1, nullptr);
    // GEMM2: out = sigmoid(H @ W2 + b2) -> f32 d_out
    gemm_kernel<1><<<dim3(OUT_F / 128, BATCH / 128), 256, SMEM_DYN>>>(b2, out);
}